// round 1
// baseline (speedup 1.0000x reference)
#include <cuda_runtime.h>

#define NB      2
#define H       48
#define W       48
#define HW      (H * W)          // 2304
#define DMODEL  768
#define DHEAD   64
#define NHEADS  12
#define M_TOT   (NB * HW)        // 4608
#define QKV_N   (3 * DMODEL)     // 2304

// Scratch (static device globals — no allocation at runtime)
__device__ float g_qkv[(size_t)M_TOT * QKV_N];   // [b*HW + s][3*768] : q|k|v per head
__device__ float g_o  [(size_t)M_TOT * DMODEL];  // [b*HW + s][head*64 + e]

// ---------------------------------------------------------------------------
// SGEMM (NT): C[m][n] = sum_k A[m][k] * B[n][k]
// BM=BN=128, BK=8, 256 threads, 8x8 per thread. Requires M%128==0, N%128==0, K%8==0.
// ---------------------------------------------------------------------------
__global__ __launch_bounds__(256) void sgemm_nt(
    const float* __restrict__ A, const float* __restrict__ B,
    float* __restrict__ C, int M, int N, int K)
{
    __shared__ float As[8][132];
    __shared__ float Bs[8][132];

    const int tid = threadIdx.x;
    const int tx = tid & 15;          // 0..15
    const int ty = tid >> 4;          // 0..15
    const int rowBase = blockIdx.y * 128;
    const int colBase = blockIdx.x * 128;

    const int lRow = tid >> 1;        // 0..127
    const int lCol = (tid & 1) * 4;   // 0 or 4

    const float* Aptr = A + (size_t)(rowBase + lRow) * K + lCol;
    const float* Bptr = B + (size_t)(colBase + lRow) * K + lCol;

    float acc[8][8];
    #pragma unroll
    for (int i = 0; i < 8; i++)
        #pragma unroll
        for (int j = 0; j < 8; j++)
            acc[i][j] = 0.0f;

    for (int k0 = 0; k0 < K; k0 += 8) {
        float4 av = *(const float4*)(Aptr + k0);
        float4 bv = *(const float4*)(Bptr + k0);
        As[lCol + 0][lRow] = av.x;
        As[lCol + 1][lRow] = av.y;
        As[lCol + 2][lRow] = av.z;
        As[lCol + 3][lRow] = av.w;
        Bs[lCol + 0][lRow] = bv.x;
        Bs[lCol + 1][lRow] = bv.y;
        Bs[lCol + 2][lRow] = bv.z;
        Bs[lCol + 3][lRow] = bv.w;
        __syncthreads();

        #pragma unroll
        for (int kk = 0; kk < 8; kk++) {
            float ra[8], rb[8];
            #pragma unroll
            for (int i = 0; i < 8; i++) ra[i] = As[kk][ty * 8 + i];
            #pragma unroll
            for (int j = 0; j < 8; j++) rb[j] = Bs[kk][tx * 8 + j];
            #pragma unroll
            for (int i = 0; i < 8; i++)
                #pragma unroll
                for (int j = 0; j < 8; j++)
                    acc[i][j] = fmaf(ra[i], rb[j], acc[i][j]);
        }
        __syncthreads();
    }

    #pragma unroll
    for (int i = 0; i < 8; i++) {
        const int r = rowBase + ty * 8 + i;
        float* Crow = C + (size_t)r * N + colBase + tx * 8;
        #pragma unroll
        for (int j = 0; j < 8; j += 4) {
            float4 v = make_float4(acc[i][j], acc[i][j+1], acc[i][j+2], acc[i][j+3]);
            *(float4*)(Crow + j) = v;
        }
    }
}

// ---------------------------------------------------------------------------
// Neighborhood attention: one warp per (batch, head, query).
// scores over keys with |qx-kx|<=ks && |qy-ky|<=ks, online softmax, o = p@v.
// Reads q/k/v slices directly out of g_qkv, writes g_o in [b][s][head*64+e].
// ---------------------------------------------------------------------------
__global__ __launch_bounds__(128) void natten_kernel(const int* __restrict__ ks_ptr)
{
    const int ks   = *ks_ptr;
    const int warp = threadIdx.x >> 5;
    const int lane = threadIdx.x & 31;
    const int q_idx = blockIdx.x * 4 + warp;
    const int head  = blockIdx.y;
    const int b     = blockIdx.z;
    if (q_idx >= HW) return;

    const int qx = q_idx / W;
    const int qy = q_idx % W;

    const float* qp = g_qkv + (size_t)(b * HW + q_idx) * QKV_N + head * DHEAD;
    const float q0 = qp[lane];
    const float q1 = qp[lane + 32];

    float m = -1e30f, l = 0.0f, a0 = 0.0f, a1 = 0.0f;

    const int x0 = max(0, qx - ks), x1 = min(H - 1, qx + ks);
    const int y0 = max(0, qy - ks), y1 = min(W - 1, qy + ks);

    for (int kx = x0; kx <= x1; kx++) {
        for (int ky = y0; ky <= y1; ky++) {
            const int kidx = kx * W + ky;
            const float* kp = g_qkv + (size_t)(b * HW + kidx) * QKV_N + DMODEL + head * DHEAD;
            float s = q0 * kp[lane] + q1 * kp[lane + 32];
            #pragma unroll
            for (int off = 16; off; off >>= 1)
                s += __shfl_xor_sync(0xffffffffu, s, off);
            s *= 0.125f;  // 1/sqrt(64)

            const float mnew = fmaxf(m, s);
            const float corr = __expf(m - mnew);
            const float p    = __expf(s - mnew);
            const float* vp = kp + DMODEL;
            l  = l  * corr + p;
            a0 = a0 * corr + p * vp[lane];
            a1 = a1 * corr + p * vp[lane + 32];
            m = mnew;
        }
    }

    const float inv = 1.0f / l;
    float* op = g_o + (size_t)(b * HW + q_idx) * DMODEL + head * DHEAD;
    op[lane]      = a0 * inv;
    op[lane + 32] = a1 * inv;
}

// ---------------------------------------------------------------------------
extern "C" void kernel_launch(void* const* d_in, const int* in_sizes, int n_in,
                              void* d_out, int out_size)
{
    const float* x      = (const float*)d_in[0];   // [2,48,48,768]
    const float* w_qkv  = (const float*)d_in[1];   // [2304,768]
    const float* w_out  = (const float*)d_in[2];   // [768,768]
    const int*   ksp    = (const int*)  d_in[3];   // scalar
    float*       out    = (float*)d_out;           // [2,48,48,768]

    float *qkv_ptr, *o_ptr;
    cudaGetSymbolAddress((void**)&qkv_ptr, g_qkv);
    cudaGetSymbolAddress((void**)&o_ptr,   g_o);

    // 1) QKV projection: [4608,768] x [2304,768]^T -> [4608,2304]
    {
        dim3 grid(QKV_N / 128, M_TOT / 128);
        sgemm_nt<<<grid, 256>>>(x, w_qkv, qkv_ptr, M_TOT, QKV_N, DMODEL);
    }

    // 2) Neighborhood attention
    {
        dim3 grid(HW / 4, NHEADS, NB);
        natten_kernel<<<grid, 128>>>(ksp);
    }

    // 3) Output projection: [4608,768] x [768,768]^T -> [4608,768] = d_out
    {
        dim3 grid(DMODEL / 128, M_TOT / 128);
        sgemm_nt<<<grid, 256>>>(o_ptr, w_out, out, M_TOT, DMODEL, DMODEL);
    }
}

// round 2
// speedup vs baseline: 1.4893x; 1.4893x over previous
#include <cuda_runtime.h>
#include <cstdint>

#define NB      2
#define H       48
#define W       48
#define HW      (H * W)          // 2304
#define DMODEL  768
#define DHEAD   64
#define NHEADS  12
#define M_TOT   (NB * HW)        // 4608
#define QKV_N   (3 * DMODEL)     // 2304

// Scratch (static device globals — no allocation at runtime)
__device__ float g_qkv[(size_t)M_TOT * QKV_N];   // [b*HW + s][3*768]
__device__ float g_o  [(size_t)M_TOT * DMODEL];  // [b*HW + s][head*64 + e]

__device__ __forceinline__ uint32_t f2tf32(float f) {
    uint32_t u;
    asm("cvt.rna.tf32.f32 %0, %1;" : "=r"(u) : "f"(f));
    return u;
}

// ---------------------------------------------------------------------------
// TF32 tensor-core GEMM (NT): C[m][n] = sum_k A[m][k] * B[n][k]
// BM=BN=128, BK=16, 256 threads (8 warps as 4x2, each warp 32x64).
// mma.sync.aligned.m16n8k8.row.col.f32.tf32.tf32.f32, fp32 accumulate.
// Requires M%128==0, N%128==0, K%16==0.
// ---------------------------------------------------------------------------
#define GBK  16
#define GPAD 8
#define GLD  (128 + GPAD)   // stride 136: bank = (8k + m) % 32 -> conflict-free frags

__global__ __launch_bounds__(256) void gemm_tf32_nt(
    const float* __restrict__ A, const float* __restrict__ B,
    float* __restrict__ C, int M, int N, int K)
{
    __shared__ uint32_t As[GBK][GLD];   // [k][m], tf32 bits
    __shared__ uint32_t Bs[GBK][GLD];   // [k][n], tf32 bits

    const int tid  = threadIdx.x;
    const int lane = tid & 31;
    const int warp = tid >> 5;
    const int wm = (warp & 3) * 32;     // warp m-offset (0..96)
    const int wn = (warp >> 2) * 64;    // warp n-offset (0 or 64)
    const int rowBase = blockIdx.y * 128;
    const int colBase = blockIdx.x * 128;

    float acc[2][8][4];
    #pragma unroll
    for (int i = 0; i < 2; i++)
        #pragma unroll
        for (int j = 0; j < 8; j++)
            #pragma unroll
            for (int t = 0; t < 4; t++)
                acc[i][j][t] = 0.0f;

    // Each thread loads 2 float4 per matrix per k-tile. L = tid*2 + {0,1}:
    // row = L>>2 (0..127), kc = (L&3)*4 (0,4,8,12).
    const int L0 = tid * 2;
    const int r0 = L0 >> 2,       kc0 = (L0 & 3) * 4;
    const int r1 = (L0 + 1) >> 2, kc1 = ((L0 + 1) & 3) * 4;
    const float* Ap0 = A + (size_t)(rowBase + r0) * K + kc0;
    const float* Ap1 = A + (size_t)(rowBase + r1) * K + kc1;
    const float* Bp0 = B + (size_t)(colBase + r0) * K + kc0;
    const float* Bp1 = B + (size_t)(colBase + r1) * K + kc1;

    for (int k0 = 0; k0 < K; k0 += GBK) {
        float4 av0 = *(const float4*)(Ap0 + k0);
        float4 av1 = *(const float4*)(Ap1 + k0);
        float4 bv0 = *(const float4*)(Bp0 + k0);
        float4 bv1 = *(const float4*)(Bp1 + k0);
        As[kc0 + 0][r0] = f2tf32(av0.x);
        As[kc0 + 1][r0] = f2tf32(av0.y);
        As[kc0 + 2][r0] = f2tf32(av0.z);
        As[kc0 + 3][r0] = f2tf32(av0.w);
        As[kc1 + 0][r1] = f2tf32(av1.x);
        As[kc1 + 1][r1] = f2tf32(av1.y);
        As[kc1 + 2][r1] = f2tf32(av1.z);
        As[kc1 + 3][r1] = f2tf32(av1.w);
        Bs[kc0 + 0][r0] = f2tf32(bv0.x);
        Bs[kc0 + 1][r0] = f2tf32(bv0.y);
        Bs[kc0 + 2][r0] = f2tf32(bv0.z);
        Bs[kc0 + 3][r0] = f2tf32(bv0.w);
        Bs[kc1 + 0][r1] = f2tf32(bv1.x);
        Bs[kc1 + 1][r1] = f2tf32(bv1.y);
        Bs[kc1 + 2][r1] = f2tf32(bv1.z);
        Bs[kc1 + 3][r1] = f2tf32(bv1.w);
        __syncthreads();

        #pragma unroll
        for (int kk = 0; kk < GBK; kk += 8) {
            const int kA = kk + (lane & 3);
            uint32_t af[2][4];
            #pragma unroll
            for (int i = 0; i < 2; i++) {
                const int rr = wm + i * 16 + (lane >> 2);
                af[i][0] = As[kA][rr];
                af[i][1] = As[kA][rr + 8];
                af[i][2] = As[kA + 4][rr];
                af[i][3] = As[kA + 4][rr + 8];
            }
            #pragma unroll
            for (int j = 0; j < 8; j++) {
                const int cc = wn + j * 8 + (lane >> 2);
                const uint32_t b0 = Bs[kA][cc];
                const uint32_t b1 = Bs[kA + 4][cc];
                #pragma unroll
                for (int i = 0; i < 2; i++) {
                    asm volatile(
                        "mma.sync.aligned.m16n8k8.row.col.f32.tf32.tf32.f32 "
                        "{%0,%1,%2,%3}, {%4,%5,%6,%7}, {%8,%9}, {%0,%1,%2,%3};"
                        : "+f"(acc[i][j][0]), "+f"(acc[i][j][1]),
                          "+f"(acc[i][j][2]), "+f"(acc[i][j][3])
                        : "r"(af[i][0]), "r"(af[i][1]), "r"(af[i][2]), "r"(af[i][3]),
                          "r"(b0), "r"(b1));
                }
            }
        }
        __syncthreads();
    }

    // Epilogue: c0/c1 at (row, col), (row, col+1); c2/c3 at row+8.
    #pragma unroll
    for (int i = 0; i < 2; i++) {
        #pragma unroll
        for (int j = 0; j < 8; j++) {
            const int row = rowBase + wm + i * 16 + (lane >> 2);
            const int col = colBase + wn + j * 8 + (lane & 3) * 2;
            float2 v01 = make_float2(acc[i][j][0], acc[i][j][1]);
            float2 v23 = make_float2(acc[i][j][2], acc[i][j][3]);
            *(float2*)(C + (size_t)row * N + col)       = v01;
            *(float2*)(C + (size_t)(row + 8) * N + col) = v23;
        }
    }
}

// ---------------------------------------------------------------------------
// Neighborhood attention: one warp per (batch, head, query).
// Scores computed 16-at-a-time per window row: independent butterfly chains
// (stage-interleaved) give ILP; one softmax update per chunk, not per key.
// ---------------------------------------------------------------------------
__global__ __launch_bounds__(128) void natten_kernel(const int* __restrict__ ks_ptr)
{
    const int ks   = *ks_ptr;
    const int warp = threadIdx.x >> 5;
    const int lane = threadIdx.x & 31;
    const int q_idx = blockIdx.x * 4 + warp;
    const int head  = blockIdx.y;
    const int b     = blockIdx.z;

    const int qx = q_idx / W;
    const int qy = q_idx % W;

    const float* qp = g_qkv + (size_t)(b * HW + q_idx) * QKV_N + head * DHEAD;
    const float q0 = qp[lane]      * 0.125f;   // fold 1/sqrt(64) into q
    const float q1 = qp[lane + 32] * 0.125f;

    float m = -1e30f, l = 0.0f, a0 = 0.0f, a1 = 0.0f;

    const int x0 = max(0, qx - ks), x1 = min(H - 1, qx + ks);
    const int y0 = max(0, qy - ks), y1 = min(W - 1, qy + ks);

    for (int kx = x0; kx <= x1; kx++) {
        const float* kbase = g_qkv + (size_t)(b * HW + kx * W) * QKV_N
                           + DMODEL + head * DHEAD;
        for (int yc = y0; yc <= y1; yc += 16) {
            const int nj = min(16, y1 - yc + 1);
            float s[16];
            #pragma unroll
            for (int j = 0; j < 16; j++) {
                if (j < nj) {
                    const float* kp = kbase + (size_t)(yc + j) * QKV_N;
                    s[j] = q0 * kp[lane] + q1 * kp[lane + 32];
                } else {
                    s[j] = -1e30f;
                }
            }
            // Interleaved butterfly: 16 independent chains per stage.
            #pragma unroll
            for (int off = 16; off; off >>= 1) {
                #pragma unroll
                for (int j = 0; j < 16; j++)
                    s[j] += __shfl_xor_sync(0xffffffffu, s[j], off);
            }

            float mrow = s[0];
            #pragma unroll
            for (int j = 1; j < 16; j++) mrow = fmaxf(mrow, s[j]);
            const float mnew = fmaxf(m, mrow);
            const float corr = __expf(m - mnew);
            m = mnew;

            float psum = 0.0f;
            #pragma unroll
            for (int j = 0; j < 16; j++) {
                s[j] = __expf(s[j] - mnew);   // padded lanes underflow to 0
                psum += s[j];
            }
            l  = l * corr + psum;
            a0 *= corr;
            a1 *= corr;

            const float* vbase = kbase + DMODEL;
            #pragma unroll
            for (int j = 0; j < 16; j++) {
                if (j < nj) {
                    const float* vp = vbase + (size_t)(yc + j) * QKV_N;
                    a0 = fmaf(s[j], vp[lane],      a0);
                    a1 = fmaf(s[j], vp[lane + 32], a1);
                }
            }
        }
    }

    const float inv = 1.0f / l;
    float* op = g_o + (size_t)(b * HW + q_idx) * DMODEL + head * DHEAD;
    op[lane]      = a0 * inv;
    op[lane + 32] = a1 * inv;
}

// ---------------------------------------------------------------------------
extern "C" void kernel_launch(void* const* d_in, const int* in_sizes, int n_in,
                              void* d_out, int out_size)
{
    const float* x      = (const float*)d_in[0];   // [2,48,48,768]
    const float* w_qkv  = (const float*)d_in[1];   // [2304,768]
    const float* w_out  = (const float*)d_in[2];   // [768,768]
    const int*   ksp    = (const int*)  d_in[3];   // scalar
    float*       out    = (float*)d_out;           // [2,48,48,768]

    float *qkv_ptr, *o_ptr;
    cudaGetSymbolAddress((void**)&qkv_ptr, g_qkv);
    cudaGetSymbolAddress((void**)&o_ptr,   g_o);

    // 1) QKV projection: [4608,768] x [2304,768]^T -> [4608,2304]
    {
        dim3 grid(QKV_N / 128, M_TOT / 128);
        gemm_tf32_nt<<<grid, 256>>>(x, w_qkv, qkv_ptr, M_TOT, QKV_N, DMODEL);
    }

    // 2) Neighborhood attention
    {
        dim3 grid(HW / 4, NHEADS, NB);
        natten_kernel<<<grid, 128>>>(ksp);
    }

    // 3) Output projection: [4608,768] x [768,768]^T -> [4608,768] = d_out
    {
        dim3 grid(DMODEL / 128, M_TOT / 128);
        gemm_tf32_nt<<<grid, 256>>>(o_ptr, w_out, out, M_TOT, DMODEL, DMODEL);
    }
}

// round 3
// speedup vs baseline: 1.5098x; 1.0138x over previous
#include <cuda_runtime.h>
#include <cstdint>

#define NB      2
#define H       48
#define W       48
#define HW      (H * W)          // 2304
#define DMODEL  768
#define DHEAD   64
#define NHEADS  12
#define M_TOT   (NB * HW)        // 4608
#define QKV_N   (3 * DMODEL)     // 2304

// Scratch (static device globals — no allocation at runtime)
__device__ float g_qkv[(size_t)M_TOT * QKV_N];   // [b*HW + s][3*768]
__device__ float g_o  [(size_t)M_TOT * DMODEL];  // [b*HW + s][head*64 + e]

__device__ __forceinline__ uint32_t f2tf32(float f) {
    uint32_t u;
    asm("cvt.rna.tf32.f32 %0, %1;" : "=r"(u) : "f"(f));
    return u;
}

// ---------------------------------------------------------------------------
// TF32 tensor-core GEMM (NT), double-buffered: C[m][n] = sum_k A[m][k]*B[n][k]
// BM=BN=128, BK=16, 256 threads (8 warps as 4x2, each warp 32x64).
// ---------------------------------------------------------------------------
#define GBK  16
#define GPAD 8
#define GLD  (128 + GPAD)   // stride 136: frag bank = (8k + m) % 32, conflict-free

__global__ __launch_bounds__(256) void gemm_tf32_nt(
    const float* __restrict__ A, const float* __restrict__ B,
    float* __restrict__ C, int M, int N, int K)
{
    __shared__ uint32_t As[2][GBK][GLD];
    __shared__ uint32_t Bs[2][GBK][GLD];

    const int tid  = threadIdx.x;
    const int lane = tid & 31;
    const int warp = tid >> 5;
    const int wm = (warp & 3) * 32;
    const int wn = (warp >> 2) * 64;
    const int rowBase = blockIdx.y * 128;
    const int colBase = blockIdx.x * 128;

    float acc[2][8][4];
    #pragma unroll
    for (int i = 0; i < 2; i++)
        #pragma unroll
        for (int j = 0; j < 8; j++)
            #pragma unroll
            for (int t = 0; t < 4; t++)
                acc[i][j][t] = 0.0f;

    // Each thread loads 2 float4 per matrix per k-tile.
    const int L0 = tid * 2;
    const int r0 = L0 >> 2,       kc0 = (L0 & 3) * 4;
    const int r1 = (L0 + 1) >> 2, kc1 = ((L0 + 1) & 3) * 4;
    const float* Ap0 = A + (size_t)(rowBase + r0) * K + kc0;
    const float* Ap1 = A + (size_t)(rowBase + r1) * K + kc1;
    const float* Bp0 = B + (size_t)(colBase + r0) * K + kc0;
    const float* Bp1 = B + (size_t)(colBase + r1) * K + kc1;

    // Prologue: tile 0 -> buffer 0
    {
        float4 av0 = *(const float4*)Ap0;
        float4 av1 = *(const float4*)Ap1;
        float4 bv0 = *(const float4*)Bp0;
        float4 bv1 = *(const float4*)Bp1;
        As[0][kc0 + 0][r0] = f2tf32(av0.x);
        As[0][kc0 + 1][r0] = f2tf32(av0.y);
        As[0][kc0 + 2][r0] = f2tf32(av0.z);
        As[0][kc0 + 3][r0] = f2tf32(av0.w);
        As[0][kc1 + 0][r1] = f2tf32(av1.x);
        As[0][kc1 + 1][r1] = f2tf32(av1.y);
        As[0][kc1 + 2][r1] = f2tf32(av1.z);
        As[0][kc1 + 3][r1] = f2tf32(av1.w);
        Bs[0][kc0 + 0][r0] = f2tf32(bv0.x);
        Bs[0][kc0 + 1][r0] = f2tf32(bv0.y);
        Bs[0][kc0 + 2][r0] = f2tf32(bv0.z);
        Bs[0][kc0 + 3][r0] = f2tf32(bv0.w);
        Bs[0][kc1 + 0][r1] = f2tf32(bv1.x);
        Bs[0][kc1 + 1][r1] = f2tf32(bv1.y);
        Bs[0][kc1 + 2][r1] = f2tf32(bv1.z);
        Bs[0][kc1 + 3][r1] = f2tf32(bv1.w);
    }
    __syncthreads();

    const int T = K / GBK;
    for (int t = 0; t < T; t++) {
        const int cur = t & 1;
        const int nxt = cur ^ 1;

        float4 av0n, av1n, bv0n, bv1n;
        const bool more = (t + 1 < T);
        if (more) {
            const int k0 = (t + 1) * GBK;
            av0n = *(const float4*)(Ap0 + k0);
            av1n = *(const float4*)(Ap1 + k0);
            bv0n = *(const float4*)(Bp0 + k0);
            bv1n = *(const float4*)(Bp1 + k0);
        }

        #pragma unroll
        for (int kk = 0; kk < GBK; kk += 8) {
            const int kA = kk + (lane & 3);
            uint32_t af[2][4];
            #pragma unroll
            for (int i = 0; i < 2; i++) {
                const int rr = wm + i * 16 + (lane >> 2);
                af[i][0] = As[cur][kA][rr];
                af[i][1] = As[cur][kA][rr + 8];
                af[i][2] = As[cur][kA + 4][rr];
                af[i][3] = As[cur][kA + 4][rr + 8];
            }
            #pragma unroll
            for (int j = 0; j < 8; j++) {
                const int cc = wn + j * 8 + (lane >> 2);
                const uint32_t b0 = Bs[cur][kA][cc];
                const uint32_t b1 = Bs[cur][kA + 4][cc];
                #pragma unroll
                for (int i = 0; i < 2; i++) {
                    asm volatile(
                        "mma.sync.aligned.m16n8k8.row.col.f32.tf32.tf32.f32 "
                        "{%0,%1,%2,%3}, {%4,%5,%6,%7}, {%8,%9}, {%0,%1,%2,%3};"
                        : "+f"(acc[i][j][0]), "+f"(acc[i][j][1]),
                          "+f"(acc[i][j][2]), "+f"(acc[i][j][3])
                        : "r"(af[i][0]), "r"(af[i][1]), "r"(af[i][2]), "r"(af[i][3]),
                          "r"(b0), "r"(b1));
                }
            }
        }

        if (more) {
            As[nxt][kc0 + 0][r0] = f2tf32(av0n.x);
            As[nxt][kc0 + 1][r0] = f2tf32(av0n.y);
            As[nxt][kc0 + 2][r0] = f2tf32(av0n.z);
            As[nxt][kc0 + 3][r0] = f2tf32(av0n.w);
            As[nxt][kc1 + 0][r1] = f2tf32(av1n.x);
            As[nxt][kc1 + 1][r1] = f2tf32(av1n.y);
            As[nxt][kc1 + 2][r1] = f2tf32(av1n.z);
            As[nxt][kc1 + 3][r1] = f2tf32(av1n.w);
            Bs[nxt][kc0 + 0][r0] = f2tf32(bv0n.x);
            Bs[nxt][kc0 + 1][r0] = f2tf32(bv0n.y);
            Bs[nxt][kc0 + 2][r0] = f2tf32(bv0n.z);
            Bs[nxt][kc0 + 3][r0] = f2tf32(bv0n.w);
            Bs[nxt][kc1 + 0][r1] = f2tf32(bv1n.x);
            Bs[nxt][kc1 + 1][r1] = f2tf32(bv1n.y);
            Bs[nxt][kc1 + 2][r1] = f2tf32(bv1n.z);
            Bs[nxt][kc1 + 3][r1] = f2tf32(bv1n.w);
        }
        __syncthreads();
    }

    #pragma unroll
    for (int i = 0; i < 2; i++) {
        #pragma unroll
        for (int j = 0; j < 8; j++) {
            const int row = rowBase + wm + i * 16 + (lane >> 2);
            const int col = colBase + wn + j * 8 + (lane & 3) * 2;
            float2 v01 = make_float2(acc[i][j][0], acc[i][j][1]);
            float2 v23 = make_float2(acc[i][j][2], acc[i][j][3]);
            *(float2*)(C + (size_t)row * N + col)       = v01;
            *(float2*)(C + (size_t)(row + 8) * N + col) = v23;
        }
    }
}

// ---------------------------------------------------------------------------
// Neighborhood attention, smem-tiled.
// CTA = (b, head, qx): 512 threads = 16 warps, each warp owns 3 queries in
// the row. Key/value rows kx stream through shared memory once per CTA
// (15x traffic reduction vs per-query streaming).
// ---------------------------------------------------------------------------
__global__ __launch_bounds__(512) void natten_kernel(const int* __restrict__ ks_ptr)
{
    __shared__ float Ks[W * DHEAD];   // 12.3 KB
    __shared__ float Vs[W * DHEAD];

    const int ks   = *ks_ptr;
    const int tid  = threadIdx.x;
    const int warp = tid >> 5;
    const int lane = tid & 31;
    const int qx   = blockIdx.x;
    const int head = blockIdx.y;
    const int b    = blockIdx.z;

    // This warp's 3 queries
    const int qy0 = warp * 3;
    float q0[3], q1[3];
    float m[3], l[3], a0[3], a1[3];
    #pragma unroll
    for (int j = 0; j < 3; j++) {
        const float* qp = g_qkv + (size_t)(b * HW + qx * W + qy0 + j) * QKV_N
                        + head * DHEAD;
        q0[j] = qp[lane]      * 0.125f;
        q1[j] = qp[lane + 32] * 0.125f;
        m[j] = -1e30f; l[j] = 0.0f; a0[j] = 0.0f; a1[j] = 0.0f;
    }

    const int x0 = max(0, qx - ks), x1 = min(H - 1, qx + ks);

    for (int kx = x0; kx <= x1; kx++) {
        // Cooperative load of K-row and V-row (48 keys x 64 dims each)
        const float* krow = g_qkv + (size_t)(b * HW + kx * W) * QKV_N
                          + DMODEL + head * DHEAD;
        const float* vrow = krow + DMODEL;
        __syncthreads();   // protect previous iteration's reads
        for (int f = tid; f < W * (DHEAD / 4); f += 512) {
            const int key = f >> 4;
            const int d4  = (f & 15) << 2;
            const size_t off = (size_t)key * QKV_N + d4;
            *(float4*)&Ks[key * DHEAD + d4] = *(const float4*)(krow + off);
            *(float4*)&Vs[key * DHEAD + d4] = *(const float4*)(vrow + off);
        }
        __syncthreads();

        #pragma unroll
        for (int j = 0; j < 3; j++) {
            const int qy = qy0 + j;
            const int y0 = max(0, qy - ks), y1 = min(W - 1, qy + ks);
            const int nj = y1 - y0 + 1;    // <= 15

            float s[16];
            #pragma unroll
            for (int u = 0; u < 16; u++) {
                if (u < nj) {
                    const float* kp = &Ks[(y0 + u) * DHEAD];
                    s[u] = q0[j] * kp[lane] + q1[j] * kp[lane + 32];
                } else {
                    s[u] = -1e30f;
                }
            }
            // Interleaved butterfly reduce: 16 independent chains per stage
            #pragma unroll
            for (int off = 16; off; off >>= 1) {
                #pragma unroll
                for (int u = 0; u < 16; u++)
                    s[u] += __shfl_xor_sync(0xffffffffu, s[u], off);
            }

            float mrow = s[0];
            #pragma unroll
            for (int u = 1; u < 16; u++) mrow = fmaxf(mrow, s[u]);
            const float mnew = fmaxf(m[j], mrow);
            const float corr = __expf(m[j] - mnew);
            m[j] = mnew;

            float psum = 0.0f;
            #pragma unroll
            for (int u = 0; u < 16; u++) {
                s[u] = __expf(s[u] - mnew);
                psum += s[u];
            }
            l[j]  = l[j] * corr + psum;
            a0[j] *= corr;
            a1[j] *= corr;

            #pragma unroll
            for (int u = 0; u < 16; u++) {
                if (u < nj) {
                    const float* vp = &Vs[(y0 + u) * DHEAD];
                    a0[j] = fmaf(s[u], vp[lane],      a0[j]);
                    a1[j] = fmaf(s[u], vp[lane + 32], a1[j]);
                }
            }
        }
    }

    #pragma unroll
    for (int j = 0; j < 3; j++) {
        const float inv = 1.0f / l[j];
        float* op = g_o + (size_t)(b * HW + qx * W + qy0 + j) * DMODEL
                  + head * DHEAD;
        op[lane]      = a0[j] * inv;
        op[lane + 32] = a1[j] * inv;
    }
}

// ---------------------------------------------------------------------------
extern "C" void kernel_launch(void* const* d_in, const int* in_sizes, int n_in,
                              void* d_out, int out_size)
{
    const float* x      = (const float*)d_in[0];   // [2,48,48,768]
    const float* w_qkv  = (const float*)d_in[1];   // [2304,768]
    const float* w_out  = (const float*)d_in[2];   // [768,768]
    const int*   ksp    = (const int*)  d_in[3];   // scalar
    float*       out    = (float*)d_out;           // [2,48,48,768]

    float *qkv_ptr, *o_ptr;
    cudaGetSymbolAddress((void**)&qkv_ptr, g_qkv);
    cudaGetSymbolAddress((void**)&o_ptr,   g_o);

    // 1) QKV projection: [4608,768] x [2304,768]^T -> [4608,2304]
    {
        dim3 grid(QKV_N / 128, M_TOT / 128);
        gemm_tf32_nt<<<grid, 256>>>(x, w_qkv, qkv_ptr, M_TOT, QKV_N, DMODEL);
    }

    // 2) Neighborhood attention (smem-tiled per query-row)
    {
        dim3 grid(H, NHEADS, NB);
        natten_kernel<<<grid, 512>>>(ksp);
    }

    // 3) Output projection: [4608,768] x [768,768]^T -> [4608,768] = d_out
    {
        dim3 grid(DMODEL / 128, M_TOT / 128);
        gemm_tf32_nt<<<grid, 256>>>(o_ptr, w_out, out, M_TOT, DMODEL, DMODEL);
    }
}

// round 5
// speedup vs baseline: 3.0126x; 1.9954x over previous
#include <cuda_runtime.h>
#include <cstdint>

#define NB      2
#define H       48
#define W       48
#define HW      (H * W)          // 2304
#define DMODEL  768
#define DHEAD   64
#define NHEADS  12
#define M_TOT   (NB * HW)        // 4608
#define QKV_N   (3 * DMODEL)     // 2304

__device__ float g_qkv[(size_t)M_TOT * QKV_N];   // [b*HW + s][3*768]
__device__ float g_o  [(size_t)M_TOT * DMODEL];  // [b*HW + s][head*64 + e]

__device__ __forceinline__ uint32_t f2tf32(float f) {
    uint32_t u;
    asm("cvt.rna.tf32.f32 %0, %1;" : "=r"(u) : "f"(f));
    return u;
}

__device__ __forceinline__ void mma_tf32(
    float& d0, float& d1, float& d2, float& d3,
    uint32_t a0, uint32_t a1, uint32_t a2, uint32_t a3,
    uint32_t b0, uint32_t b1)
{
    asm volatile(
        "mma.sync.aligned.m16n8k8.row.col.f32.tf32.tf32.f32 "
        "{%0,%1,%2,%3}, {%4,%5,%6,%7}, {%8,%9}, {%0,%1,%2,%3};"
        : "+f"(d0), "+f"(d1), "+f"(d2), "+f"(d3)
        : "r"(a0), "r"(a1), "r"(a2), "r"(a3), "r"(b0), "r"(b1));
}

// ---------------------------------------------------------------------------
// TF32 tensor-core GEMM (NT), double-buffered (unchanged — validated R2/R3).
// ---------------------------------------------------------------------------
#define GBK  16
#define GPAD 8
#define GLD  (128 + GPAD)

__global__ __launch_bounds__(256) void gemm_tf32_nt(
    const float* __restrict__ A, const float* __restrict__ B,
    float* __restrict__ C, int M, int N, int K)
{
    __shared__ uint32_t As[2][GBK][GLD];
    __shared__ uint32_t Bs[2][GBK][GLD];

    const int tid  = threadIdx.x;
    const int lane = tid & 31;
    const int warp = tid >> 5;
    const int wm = (warp & 3) * 32;
    const int wn = (warp >> 2) * 64;
    const int rowBase = blockIdx.y * 128;
    const int colBase = blockIdx.x * 128;

    float acc[2][8][4];
    #pragma unroll
    for (int i = 0; i < 2; i++)
        #pragma unroll
        for (int j = 0; j < 8; j++)
            #pragma unroll
            for (int t = 0; t < 4; t++)
                acc[i][j][t] = 0.0f;

    const int L0 = tid * 2;
    const int r0 = L0 >> 2,       kc0 = (L0 & 3) * 4;
    const int r1 = (L0 + 1) >> 2, kc1 = ((L0 + 1) & 3) * 4;
    const float* Ap0 = A + (size_t)(rowBase + r0) * K + kc0;
    const float* Ap1 = A + (size_t)(rowBase + r1) * K + kc1;
    const float* Bp0 = B + (size_t)(colBase + r0) * K + kc0;
    const float* Bp1 = B + (size_t)(colBase + r1) * K + kc1;

    {
        float4 av0 = *(const float4*)Ap0;
        float4 av1 = *(const float4*)Ap1;
        float4 bv0 = *(const float4*)Bp0;
        float4 bv1 = *(const float4*)Bp1;
        As[0][kc0 + 0][r0] = f2tf32(av0.x);
        As[0][kc0 + 1][r0] = f2tf32(av0.y);
        As[0][kc0 + 2][r0] = f2tf32(av0.z);
        As[0][kc0 + 3][r0] = f2tf32(av0.w);
        As[0][kc1 + 0][r1] = f2tf32(av1.x);
        As[0][kc1 + 1][r1] = f2tf32(av1.y);
        As[0][kc1 + 2][r1] = f2tf32(av1.z);
        As[0][kc1 + 3][r1] = f2tf32(av1.w);
        Bs[0][kc0 + 0][r0] = f2tf32(bv0.x);
        Bs[0][kc0 + 1][r0] = f2tf32(bv0.y);
        Bs[0][kc0 + 2][r0] = f2tf32(bv0.z);
        Bs[0][kc0 + 3][r0] = f2tf32(bv0.w);
        Bs[0][kc1 + 0][r1] = f2tf32(bv1.x);
        Bs[0][kc1 + 1][r1] = f2tf32(bv1.y);
        Bs[0][kc1 + 2][r1] = f2tf32(bv1.z);
        Bs[0][kc1 + 3][r1] = f2tf32(bv1.w);
    }
    __syncthreads();

    const int T = K / GBK;
    for (int t = 0; t < T; t++) {
        const int cur = t & 1;
        const int nxt = cur ^ 1;

        float4 av0n, av1n, bv0n, bv1n;
        const bool more = (t + 1 < T);
        if (more) {
            const int k0 = (t + 1) * GBK;
            av0n = *(const float4*)(Ap0 + k0);
            av1n = *(const float4*)(Ap1 + k0);
            bv0n = *(const float4*)(Bp0 + k0);
            bv1n = *(const float4*)(Bp1 + k0);
        }

        #pragma unroll
        for (int kk = 0; kk < GBK; kk += 8) {
            const int kA = kk + (lane & 3);
            uint32_t af[2][4];
            #pragma unroll
            for (int i = 0; i < 2; i++) {
                const int rr = wm + i * 16 + (lane >> 2);
                af[i][0] = As[cur][kA][rr];
                af[i][1] = As[cur][kA][rr + 8];
                af[i][2] = As[cur][kA + 4][rr];
                af[i][3] = As[cur][kA + 4][rr + 8];
            }
            #pragma unroll
            for (int j = 0; j < 8; j++) {
                const int cc = wn + j * 8 + (lane >> 2);
                const uint32_t b0 = Bs[cur][kA][cc];
                const uint32_t b1 = Bs[cur][kA + 4][cc];
                #pragma unroll
                for (int i = 0; i < 2; i++)
                    mma_tf32(acc[i][j][0], acc[i][j][1], acc[i][j][2], acc[i][j][3],
                             af[i][0], af[i][1], af[i][2], af[i][3], b0, b1);
            }
        }

        if (more) {
            As[nxt][kc0 + 0][r0] = f2tf32(av0n.x);
            As[nxt][kc0 + 1][r0] = f2tf32(av0n.y);
            As[nxt][kc0 + 2][r0] = f2tf32(av0n.z);
            As[nxt][kc0 + 3][r0] = f2tf32(av0n.w);
            As[nxt][kc1 + 0][r1] = f2tf32(av1n.x);
            As[nxt][kc1 + 1][r1] = f2tf32(av1n.y);
            As[nxt][kc1 + 2][r1] = f2tf32(av1n.z);
            As[nxt][kc1 + 3][r1] = f2tf32(av1n.w);
            Bs[nxt][kc0 + 0][r0] = f2tf32(bv0n.x);
            Bs[nxt][kc0 + 1][r0] = f2tf32(bv0n.y);
            Bs[nxt][kc0 + 2][r0] = f2tf32(bv0n.z);
            Bs[nxt][kc0 + 3][r0] = f2tf32(bv0n.w);
            Bs[nxt][kc1 + 0][r1] = f2tf32(bv1n.x);
            Bs[nxt][kc1 + 1][r1] = f2tf32(bv1n.y);
            Bs[nxt][kc1 + 2][r1] = f2tf32(bv1n.z);
            Bs[nxt][kc1 + 3][r1] = f2tf32(bv1n.w);
        }
        __syncthreads();
    }

    #pragma unroll
    for (int i = 0; i < 2; i++) {
        #pragma unroll
        for (int j = 0; j < 8; j++) {
            const int row = rowBase + wm + i * 16 + (lane >> 2);
            const int col = colBase + wn + j * 8 + (lane & 3) * 2;
            float2 v01 = make_float2(acc[i][j][0], acc[i][j][1]);
            float2 v23 = make_float2(acc[i][j][2], acc[i][j][3]);
            *(float2*)(C + (size_t)row * N + col)       = v01;
            *(float2*)(C + (size_t)(row + 8) * N + col) = v23;
        }
    }
}

// ---------------------------------------------------------------------------
// Tensor-core neighborhood attention (R4 design, fixed smem strides).
// CTA = (qx, head, b), 96 threads = 3 warps; warp w owns query rows
// [w*16, w*16+16). Per key-row kx: S = Q.K^T (MMA), register mask, online
// softmax, P staged in smem (tf32), O += P.V (MMA).
//
// Strides: Q/K rows hold 64 tf32 -> stride 68 (bank = 4r+j, conflict-free).
// V: stride 64 with XOR swizzle col^((ky&3)<<3) (bank = 8(nt^j)+r, c-free).
// P rows hold 48 -> stride 50. Total smem = 48000 B.
// ---------------------------------------------------------------------------
#define QK_LD 68
#define PS_LD 50

__global__ __launch_bounds__(96) void natten_mma(const int* __restrict__ ks_ptr)
{
    __shared__ uint32_t Qs[48 * QK_LD];   // 13056 B
    __shared__ uint32_t Ks[48 * QK_LD];   // 13056 B
    __shared__ uint32_t Vs[48 * 64];      // 12288 B (swizzled)
    __shared__ uint32_t Ps[48 * PS_LD];   //  9600 B

    const int ks   = *ks_ptr;
    const int tid  = threadIdx.x;
    const int lane = tid & 31;
    const int warp = tid >> 5;
    const int qx   = blockIdx.x;
    const int head = blockIdx.y;
    const int b    = blockIdx.z;

    const int r = lane >> 2;     // 0..7
    const int j = lane & 3;      // 0..3
    const int grow = warp * 16 + r;   // query y for c0/c1 (grow+8 for c2/c3)

    // Load Q row-block (48x64), fold 1/8 scale, convert to tf32.
    const float* qbase = g_qkv + (size_t)(b * HW + qx * W) * QKV_N + head * DHEAD;
    for (int i = tid; i < 48 * 16; i += 96) {
        const int row = i >> 4, d4 = (i & 15) << 2;
        float4 v = *(const float4*)(qbase + (size_t)row * QKV_N + d4);
        uint32_t* p = &Qs[row * QK_LD + d4];
        p[0] = f2tf32(v.x * 0.125f);
        p[1] = f2tf32(v.y * 0.125f);
        p[2] = f2tf32(v.z * 0.125f);
        p[3] = f2tf32(v.w * 0.125f);
    }

    float o[8][4];
    #pragma unroll
    for (int nt = 0; nt < 8; nt++)
        #pragma unroll
        for (int t = 0; t < 4; t++)
            o[nt][t] = 0.0f;
    float m0 = -1e30f, m1 = -1e30f, l0 = 0.0f, l1 = 0.0f;

    const int x0 = max(0, qx - ks), x1 = min(H - 1, qx + ks);

    for (int kx = x0; kx <= x1; kx++) {
        __syncthreads();   // previous iteration's MMA reads done
        const float* krow = g_qkv + (size_t)(b * HW + kx * W) * QKV_N
                          + DMODEL + head * DHEAD;
        const float* vrow = krow + DMODEL;
        for (int i = tid; i < 48 * 16; i += 96) {
            const int key = i >> 4, d4 = (i & 15) << 2;
            const size_t off = (size_t)key * QKV_N + d4;
            float4 kv = *(const float4*)(krow + off);
            float4 vv = *(const float4*)(vrow + off);
            uint32_t* pk = &Ks[key * QK_LD + d4];
            pk[0] = f2tf32(kv.x); pk[1] = f2tf32(kv.y);
            pk[2] = f2tf32(kv.z); pk[3] = f2tf32(kv.w);
            uint32_t* pv = &Vs[key * 64 + (d4 ^ ((key & 3) << 3))];
            pv[0] = f2tf32(vv.x); pv[1] = f2tf32(vv.y);
            pv[2] = f2tf32(vv.z); pv[3] = f2tf32(vv.w);
        }
        __syncthreads();

        // ---- S = Q . K^T : 16x48 per warp ----
        float sc[6][4];
        #pragma unroll
        for (int nt = 0; nt < 6; nt++)
            #pragma unroll
            for (int t = 0; t < 4; t++)
                sc[nt][t] = 0.0f;

        #pragma unroll
        for (int kk = 0; kk < 8; kk++) {
            const uint32_t a0 = Qs[(warp * 16 + r)     * QK_LD + kk * 8 + j];
            const uint32_t a1 = Qs[(warp * 16 + r + 8) * QK_LD + kk * 8 + j];
            const uint32_t a2 = Qs[(warp * 16 + r)     * QK_LD + kk * 8 + j + 4];
            const uint32_t a3 = Qs[(warp * 16 + r + 8) * QK_LD + kk * 8 + j + 4];
            #pragma unroll
            for (int nt = 0; nt < 6; nt++) {
                const uint32_t b0 = Ks[(nt * 8 + r) * QK_LD + kk * 8 + j];
                const uint32_t b1 = Ks[(nt * 8 + r) * QK_LD + kk * 8 + j + 4];
                mma_tf32(sc[nt][0], sc[nt][1], sc[nt][2], sc[nt][3],
                         a0, a1, a2, a3, b0, b1);
            }
        }

        // ---- mask + online softmax ----
        float rmax0 = -1e30f, rmax1 = -1e30f;
        #pragma unroll
        for (int nt = 0; nt < 6; nt++) {
            const int ky0 = nt * 8 + 2 * j;
            const int ky1 = ky0 + 1;
            if (abs(grow - ky0) > ks)     sc[nt][0] = -1e30f;
            if (abs(grow - ky1) > ks)     sc[nt][1] = -1e30f;
            if (abs(grow + 8 - ky0) > ks) sc[nt][2] = -1e30f;
            if (abs(grow + 8 - ky1) > ks) sc[nt][3] = -1e30f;
            rmax0 = fmaxf(rmax0, fmaxf(sc[nt][0], sc[nt][1]));
            rmax1 = fmaxf(rmax1, fmaxf(sc[nt][2], sc[nt][3]));
        }
        rmax0 = fmaxf(rmax0, __shfl_xor_sync(0xffffffffu, rmax0, 1));
        rmax0 = fmaxf(rmax0, __shfl_xor_sync(0xffffffffu, rmax0, 2));
        rmax1 = fmaxf(rmax1, __shfl_xor_sync(0xffffffffu, rmax1, 1));
        rmax1 = fmaxf(rmax1, __shfl_xor_sync(0xffffffffu, rmax1, 2));

        const float mn0 = fmaxf(m0, rmax0);
        const float mn1 = fmaxf(m1, rmax1);
        const float cr0 = __expf(m0 - mn0);
        const float cr1 = __expf(m1 - mn1);
        m0 = mn0; m1 = mn1;

        float ps0 = 0.0f, ps1 = 0.0f;
        #pragma unroll
        for (int nt = 0; nt < 6; nt++) {
            sc[nt][0] = __expf(sc[nt][0] - mn0);
            sc[nt][1] = __expf(sc[nt][1] - mn0);
            sc[nt][2] = __expf(sc[nt][2] - mn1);
            sc[nt][3] = __expf(sc[nt][3] - mn1);
            ps0 += sc[nt][0] + sc[nt][1];
            ps1 += sc[nt][2] + sc[nt][3];
        }
        ps0 += __shfl_xor_sync(0xffffffffu, ps0, 1);
        ps0 += __shfl_xor_sync(0xffffffffu, ps0, 2);
        ps1 += __shfl_xor_sync(0xffffffffu, ps1, 1);
        ps1 += __shfl_xor_sync(0xffffffffu, ps1, 2);
        l0 = l0 * cr0 + ps0;
        l1 = l1 * cr1 + ps1;

        #pragma unroll
        for (int nt = 0; nt < 8; nt++) {
            o[nt][0] *= cr0; o[nt][1] *= cr0;
            o[nt][2] *= cr1; o[nt][3] *= cr1;
        }

        // ---- stage P (tf32) in smem ----
        #pragma unroll
        for (int nt = 0; nt < 6; nt++) {
            uint2 p01 = make_uint2(f2tf32(sc[nt][0]), f2tf32(sc[nt][1]));
            uint2 p23 = make_uint2(f2tf32(sc[nt][2]), f2tf32(sc[nt][3]));
            *(uint2*)&Ps[(grow)     * PS_LD + nt * 8 + 2 * j] = p01;
            *(uint2*)&Ps[(grow + 8) * PS_LD + nt * 8 + 2 * j] = p23;
        }
        __syncwarp();   // P tile is warp-private (own 16 rows)

        // ---- O += P . V : 16x64 per warp ----
        #pragma unroll
        for (int kk = 0; kk < 6; kk++) {
            const uint32_t a0 = Ps[(warp * 16 + r)     * PS_LD + kk * 8 + j];
            const uint32_t a1 = Ps[(warp * 16 + r + 8) * PS_LD + kk * 8 + j];
            const uint32_t a2 = Ps[(warp * 16 + r)     * PS_LD + kk * 8 + j + 4];
            const uint32_t a3 = Ps[(warp * 16 + r + 8) * PS_LD + kk * 8 + j + 4];
            const int sw = j << 3;   // (ky & 3) << 3, same for ky and ky+4
            #pragma unroll
            for (int nt = 0; nt < 8; nt++) {
                const int col = (nt * 8 + r) ^ sw;
                const uint32_t b0 = Vs[(kk * 8 + j)     * 64 + col];
                const uint32_t b1 = Vs[(kk * 8 + j + 4) * 64 + col];
                mma_tf32(o[nt][0], o[nt][1], o[nt][2], o[nt][3],
                         a0, a1, a2, a3, b0, b1);
            }
        }
    }

    // ---- writeout ----
    const float inv0 = 1.0f / l0;
    const float inv1 = 1.0f / l1;
    float* ob0 = g_o + (size_t)(b * HW + qx * W + grow)     * DMODEL + head * DHEAD;
    float* ob1 = g_o + (size_t)(b * HW + qx * W + grow + 8) * DMODEL + head * DHEAD;
    #pragma unroll
    for (int nt = 0; nt < 8; nt++) {
        const int col = nt * 8 + 2 * j;
        *(float2*)(ob0 + col) = make_float2(o[nt][0] * inv0, o[nt][1] * inv0);
        *(float2*)(ob1 + col) = make_float2(o[nt][2] * inv1, o[nt][3] * inv1);
    }
}

// ---------------------------------------------------------------------------
extern "C" void kernel_launch(void* const* d_in, const int* in_sizes, int n_in,
                              void* d_out, int out_size)
{
    const float* x      = (const float*)d_in[0];
    const float* w_qkv  = (const float*)d_in[1];
    const float* w_out  = (const float*)d_in[2];
    const int*   ksp    = (const int*)  d_in[3];
    float*       out    = (float*)d_out;

    float *qkv_ptr, *o_ptr;
    cudaGetSymbolAddress((void**)&qkv_ptr, g_qkv);
    cudaGetSymbolAddress((void**)&o_ptr,   g_o);

    // 1) QKV projection
    {
        dim3 grid(QKV_N / 128, M_TOT / 128);
        gemm_tf32_nt<<<grid, 256>>>(x, w_qkv, qkv_ptr, M_TOT, QKV_N, DMODEL);
    }

    // 2) Tensor-core neighborhood attention
    {
        dim3 grid(H, NHEADS, NB);
        natten_mma<<<grid, 96>>>(ksp);
    }

    // 3) Output projection
    {
        dim3 grid(DMODEL / 128, M_TOT / 128);
        gemm_tf32_nt<<<grid, 256>>>(o_ptr, w_out, out, M_TOT, DMODEL, DMODEL);
    }
}

// round 6
// speedup vs baseline: 3.2756x; 1.0873x over previous
#include <cuda_runtime.h>
#include <cstdint>

#define NB      2
#define H       48
#define W       48
#define HW      (H * W)          // 2304
#define DMODEL  768
#define DHEAD   64
#define NHEADS  12
#define M_TOT   (NB * HW)        // 4608
#define QKV_N   (3 * DMODEL)     // 2304

__device__ float g_qkv[(size_t)M_TOT * QKV_N];   // tf32 values: q|k|v
__device__ float g_o  [(size_t)M_TOT * DMODEL];  // tf32 values
__device__ float g_xt [(size_t)M_TOT * DMODEL];  // x, tf32
__device__ float g_wqt[(size_t)QKV_N * DMODEL];  // w_qkv, tf32
__device__ float g_wot[(size_t)DMODEL * DMODEL]; // w_out, tf32

__device__ __forceinline__ uint32_t f2tf32(float f) {
    uint32_t u;
    asm("cvt.rna.tf32.f32 %0, %1;" : "=r"(u) : "f"(f));
    return u;
}

__device__ __forceinline__ void mma_tf32(
    float& d0, float& d1, float& d2, float& d3,
    uint32_t a0, uint32_t a1, uint32_t a2, uint32_t a3,
    uint32_t b0, uint32_t b1)
{
    asm volatile(
        "mma.sync.aligned.m16n8k8.row.col.f32.tf32.tf32.f32 "
        "{%0,%1,%2,%3}, {%4,%5,%6,%7}, {%8,%9}, {%0,%1,%2,%3};"
        : "+f"(d0), "+f"(d1), "+f"(d2), "+f"(d3)
        : "r"(a0), "r"(a1), "r"(a2), "r"(a3), "r"(b0), "r"(b1));
}

__device__ __forceinline__ void cp16(uint32_t saddr, const void* g) {
    asm volatile("cp.async.cg.shared.global [%0], [%1], 16;"
                 :: "r"(saddr), "l"(g));
}
__device__ __forceinline__ uint32_t s2u(const void* p) {
    return (uint32_t)__cvta_generic_to_shared(p);
}

// ---------------------------------------------------------------------------
// Elementwise tf32 pre-convert (float4 vectorized).
// ---------------------------------------------------------------------------
__global__ void cvt_kernel(const float* __restrict__ src, float* __restrict__ dst, int n4)
{
    int i = blockIdx.x * blockDim.x + threadIdx.x;
    const int stride = gridDim.x * blockDim.x;
    for (; i < n4; i += stride) {
        float4 v = ((const float4*)src)[i];
        v.x = __uint_as_float(f2tf32(v.x));
        v.y = __uint_as_float(f2tf32(v.y));
        v.z = __uint_as_float(f2tf32(v.z));
        v.w = __uint_as_float(f2tf32(v.w));
        ((float4*)dst)[i] = v;
    }
}

// ---------------------------------------------------------------------------
// TF32 GEMM (NT) with cp.async 2-stage pipeline. Inputs already tf32 values.
// BM=BN=128, BK=16, 256 threads, 8 warps (4x2), warp tile 32x64.
// smem [m][k] layout, stride 20 words (conflict-free fragment banks).
// store_tf32: epilogue rounds C to tf32 (for tensors consumed by MMA later).
// ---------------------------------------------------------------------------
#define ALD 20

__global__ __launch_bounds__(256) void gemm_tf32_async(
    const float* __restrict__ A, const float* __restrict__ B,
    float* __restrict__ C, int M, int N, int K, int store_tf32)
{
    __shared__ uint32_t As[2][128][ALD];   // 20480 B
    __shared__ uint32_t Bs[2][128][ALD];   // 20480 B

    const int tid  = threadIdx.x;
    const int lane = tid & 31;
    const int warp = tid >> 5;
    const int wm = (warp & 3) * 32;
    const int wn = (warp >> 2) * 64;
    const int rowBase = blockIdx.y * 128;
    const int colBase = blockIdx.x * 128;
    const int r = lane >> 2;   // 0..7
    const int q = lane & 3;    // 0..3

    float acc[2][8][4];
    #pragma unroll
    for (int i = 0; i < 2; i++)
        #pragma unroll
        for (int jn = 0; jn < 8; jn++)
            #pragma unroll
            for (int t = 0; t < 4; t++)
                acc[i][jn][t] = 0.0f;

    // Copy mapping: 512 16B chunks per matrix per stage, 2 per thread.
    const int L0 = tid * 2;
    const int r0 = L0 >> 2,       kc0 = (L0 & 3) * 4;
    const int r1 = (L0 + 1) >> 2, kc1 = ((L0 + 1) & 3) * 4;
    const float* Ap0 = A + (size_t)(rowBase + r0) * K + kc0;
    const float* Ap1 = A + (size_t)(rowBase + r1) * K + kc1;
    const float* Bp0 = B + (size_t)(colBase + r0) * K + kc0;
    const float* Bp1 = B + (size_t)(colBase + r1) * K + kc1;

    uint32_t sA0[2], sA1[2], sB0[2], sB1[2];
    #pragma unroll
    for (int s = 0; s < 2; s++) {
        sA0[s] = s2u(&As[s][r0][kc0]);
        sA1[s] = s2u(&As[s][r1][kc1]);
        sB0[s] = s2u(&Bs[s][r0][kc0]);
        sB1[s] = s2u(&Bs[s][r1][kc1]);
    }

    // Prologue: stage 0
    cp16(sA0[0], Ap0); cp16(sA1[0], Ap1);
    cp16(sB0[0], Bp0); cp16(sB1[0], Bp1);
    asm volatile("cp.async.commit_group;");

    const int T = K / 16;
    for (int t = 0; t < T; t++) {
        const int cur = t & 1;
        const int nxt = cur ^ 1;
        const bool more = (t + 1 < T);
        if (more) {
            const int k0 = (t + 1) * 16;
            cp16(sA0[nxt], Ap0 + k0); cp16(sA1[nxt], Ap1 + k0);
            cp16(sB0[nxt], Bp0 + k0); cp16(sB1[nxt], Bp1 + k0);
            asm volatile("cp.async.commit_group;");
            asm volatile("cp.async.wait_group 1;");
        } else {
            asm volatile("cp.async.wait_group 0;");
        }
        __syncthreads();

        #pragma unroll
        for (int kk = 0; kk < 16; kk += 8) {
            const int kA = kk + q;
            uint32_t af[2][4];
            #pragma unroll
            for (int i = 0; i < 2; i++) {
                const int rr = wm + i * 16 + r;
                af[i][0] = As[cur][rr][kA];
                af[i][1] = As[cur][rr + 8][kA];
                af[i][2] = As[cur][rr][kA + 4];
                af[i][3] = As[cur][rr + 8][kA + 4];
            }
            #pragma unroll
            for (int jn = 0; jn < 8; jn++) {
                const int cc = wn + jn * 8 + r;
                const uint32_t b0 = Bs[cur][cc][kA];
                const uint32_t b1 = Bs[cur][cc][kA + 4];
                #pragma unroll
                for (int i = 0; i < 2; i++)
                    mma_tf32(acc[i][jn][0], acc[i][jn][1], acc[i][jn][2], acc[i][jn][3],
                             af[i][0], af[i][1], af[i][2], af[i][3], b0, b1);
            }
        }
        __syncthreads();   // buffer cur reused by copy at t+2
    }

    #pragma unroll
    for (int i = 0; i < 2; i++) {
        #pragma unroll
        for (int jn = 0; jn < 8; jn++) {
            const int row = rowBase + wm + i * 16 + r;
            const int col = colBase + wn + jn * 8 + q * 2;
            float v0 = acc[i][jn][0], v1 = acc[i][jn][1];
            float v2 = acc[i][jn][2], v3 = acc[i][jn][3];
            if (store_tf32) {
                v0 = __uint_as_float(f2tf32(v0));
                v1 = __uint_as_float(f2tf32(v1));
                v2 = __uint_as_float(f2tf32(v2));
                v3 = __uint_as_float(f2tf32(v3));
            }
            *(float2*)(C + (size_t)row * N + col)       = make_float2(v0, v1);
            *(float2*)(C + (size_t)(row + 8) * N + col) = make_float2(v2, v3);
        }
    }
}

// ---------------------------------------------------------------------------
// Tensor-core neighborhood attention (R5 design; g_qkv already tf32 so K/V
// fills are raw uint4 copies, Q scaled by exact power of two).
// ---------------------------------------------------------------------------
#define QK_LD 68
#define PS_LD 50

__global__ __launch_bounds__(96) void natten_mma(const int* __restrict__ ks_ptr)
{
    __shared__ uint32_t Qs[48 * QK_LD];
    __shared__ uint32_t Ks[48 * QK_LD];
    __shared__ uint32_t Vs[48 * 64];      // swizzled
    __shared__ uint32_t Ps[48 * PS_LD];

    const int ks   = *ks_ptr;
    const int tid  = threadIdx.x;
    const int lane = tid & 31;
    const int warp = tid >> 5;
    const int qx   = blockIdx.x;
    const int head = blockIdx.y;
    const int b    = blockIdx.z;

    const int r = lane >> 2;
    const int j = lane & 3;
    const int grow = warp * 16 + r;

    // Q row-block: tf32 values * 0.125 (exact) -> bits
    const float* qbase = g_qkv + (size_t)(b * HW + qx * W) * QKV_N + head * DHEAD;
    for (int i = tid; i < 48 * 16; i += 96) {
        const int row = i >> 4, d4 = (i & 15) << 2;
        float4 v = *(const float4*)(qbase + (size_t)row * QKV_N + d4);
        uint32_t* p = &Qs[row * QK_LD + d4];
        p[0] = __float_as_uint(v.x * 0.125f);
        p[1] = __float_as_uint(v.y * 0.125f);
        p[2] = __float_as_uint(v.z * 0.125f);
        p[3] = __float_as_uint(v.w * 0.125f);
    }

    float o[8][4];
    #pragma unroll
    for (int nt = 0; nt < 8; nt++)
        #pragma unroll
        for (int t = 0; t < 4; t++)
            o[nt][t] = 0.0f;
    float m0 = -1e30f, m1 = -1e30f, l0 = 0.0f, l1 = 0.0f;

    const int x0 = max(0, qx - ks), x1 = min(H - 1, qx + ks);

    for (int kx = x0; kx <= x1; kx++) {
        __syncthreads();
        const float* krow = g_qkv + (size_t)(b * HW + kx * W) * QKV_N
                          + DMODEL + head * DHEAD;
        const float* vrow = krow + DMODEL;
        for (int i = tid; i < 48 * 16; i += 96) {
            const int key = i >> 4, d4 = (i & 15) << 2;
            const size_t off = (size_t)key * QKV_N + d4;
            uint4 kv = *(const uint4*)(krow + off);
            uint4 vv = *(const uint4*)(vrow + off);
            *(uint4*)&Ks[key * QK_LD + d4] = kv;
            *(uint4*)&Vs[key * 64 + (d4 ^ ((key & 3) << 3))] = vv;
        }
        __syncthreads();

        // ---- S = Q . K^T : 16x48 per warp ----
        float sc[6][4];
        #pragma unroll
        for (int nt = 0; nt < 6; nt++)
            #pragma unroll
            for (int t = 0; t < 4; t++)
                sc[nt][t] = 0.0f;

        #pragma unroll
        for (int kk = 0; kk < 8; kk++) {
            const uint32_t a0 = Qs[(warp * 16 + r)     * QK_LD + kk * 8 + j];
            const uint32_t a1 = Qs[(warp * 16 + r + 8) * QK_LD + kk * 8 + j];
            const uint32_t a2 = Qs[(warp * 16 + r)     * QK_LD + kk * 8 + j + 4];
            const uint32_t a3 = Qs[(warp * 16 + r + 8) * QK_LD + kk * 8 + j + 4];
            #pragma unroll
            for (int nt = 0; nt < 6; nt++) {
                const uint32_t b0 = Ks[(nt * 8 + r) * QK_LD + kk * 8 + j];
                const uint32_t b1 = Ks[(nt * 8 + r) * QK_LD + kk * 8 + j + 4];
                mma_tf32(sc[nt][0], sc[nt][1], sc[nt][2], sc[nt][3],
                         a0, a1, a2, a3, b0, b1);
            }
        }

        // ---- mask + online softmax ----
        float rmax0 = -1e30f, rmax1 = -1e30f;
        #pragma unroll
        for (int nt = 0; nt < 6; nt++) {
            const int ky0 = nt * 8 + 2 * j;
            const int ky1 = ky0 + 1;
            if (abs(grow - ky0) > ks)     sc[nt][0] = -1e30f;
            if (abs(grow - ky1) > ks)     sc[nt][1] = -1e30f;
            if (abs(grow + 8 - ky0) > ks) sc[nt][2] = -1e30f;
            if (abs(grow + 8 - ky1) > ks) sc[nt][3] = -1e30f;
            rmax0 = fmaxf(rmax0, fmaxf(sc[nt][0], sc[nt][1]));
            rmax1 = fmaxf(rmax1, fmaxf(sc[nt][2], sc[nt][3]));
        }
        rmax0 = fmaxf(rmax0, __shfl_xor_sync(0xffffffffu, rmax0, 1));
        rmax0 = fmaxf(rmax0, __shfl_xor_sync(0xffffffffu, rmax0, 2));
        rmax1 = fmaxf(rmax1, __shfl_xor_sync(0xffffffffu, rmax1, 1));
        rmax1 = fmaxf(rmax1, __shfl_xor_sync(0xffffffffu, rmax1, 2));

        const float mn0 = fmaxf(m0, rmax0);
        const float mn1 = fmaxf(m1, rmax1);
        const float cr0 = __expf(m0 - mn0);
        const float cr1 = __expf(m1 - mn1);
        m0 = mn0; m1 = mn1;

        float ps0 = 0.0f, ps1 = 0.0f;
        #pragma unroll
        for (int nt = 0; nt < 6; nt++) {
            sc[nt][0] = __expf(sc[nt][0] - mn0);
            sc[nt][1] = __expf(sc[nt][1] - mn0);
            sc[nt][2] = __expf(sc[nt][2] - mn1);
            sc[nt][3] = __expf(sc[nt][3] - mn1);
            ps0 += sc[nt][0] + sc[nt][1];
            ps1 += sc[nt][2] + sc[nt][3];
        }
        ps0 += __shfl_xor_sync(0xffffffffu, ps0, 1);
        ps0 += __shfl_xor_sync(0xffffffffu, ps0, 2);
        ps1 += __shfl_xor_sync(0xffffffffu, ps1, 1);
        ps1 += __shfl_xor_sync(0xffffffffu, ps1, 2);
        l0 = l0 * cr0 + ps0;
        l1 = l1 * cr1 + ps1;

        #pragma unroll
        for (int nt = 0; nt < 8; nt++) {
            o[nt][0] *= cr0; o[nt][1] *= cr0;
            o[nt][2] *= cr1; o[nt][3] *= cr1;
        }

        // ---- stage P (tf32) in smem ----
        #pragma unroll
        for (int nt = 0; nt < 6; nt++) {
            uint2 p01 = make_uint2(f2tf32(sc[nt][0]), f2tf32(sc[nt][1]));
            uint2 p23 = make_uint2(f2tf32(sc[nt][2]), f2tf32(sc[nt][3]));
            *(uint2*)&Ps[(grow)     * PS_LD + nt * 8 + 2 * j] = p01;
            *(uint2*)&Ps[(grow + 8) * PS_LD + nt * 8 + 2 * j] = p23;
        }
        __syncwarp();

        // ---- O += P . V : 16x64 per warp ----
        #pragma unroll
        for (int kk = 0; kk < 6; kk++) {
            const uint32_t a0 = Ps[(warp * 16 + r)     * PS_LD + kk * 8 + j];
            const uint32_t a1 = Ps[(warp * 16 + r + 8) * PS_LD + kk * 8 + j];
            const uint32_t a2 = Ps[(warp * 16 + r)     * PS_LD + kk * 8 + j + 4];
            const uint32_t a3 = Ps[(warp * 16 + r + 8) * PS_LD + kk * 8 + j + 4];
            const int sw = j << 3;
            #pragma unroll
            for (int nt = 0; nt < 8; nt++) {
                const int col = (nt * 8 + r) ^ sw;
                const uint32_t b0 = Vs[(kk * 8 + j)     * 64 + col];
                const uint32_t b1 = Vs[(kk * 8 + j + 4) * 64 + col];
                mma_tf32(o[nt][0], o[nt][1], o[nt][2], o[nt][3],
                         a0, a1, a2, a3, b0, b1);
            }
        }
    }

    // ---- writeout (tf32-rounded: consumed by out-proj MMA) ----
    const float inv0 = 1.0f / l0;
    const float inv1 = 1.0f / l1;
    float* ob0 = g_o + (size_t)(b * HW + qx * W + grow)     * DMODEL + head * DHEAD;
    float* ob1 = g_o + (size_t)(b * HW + qx * W + grow + 8) * DMODEL + head * DHEAD;
    #pragma unroll
    for (int nt = 0; nt < 8; nt++) {
        const int col = nt * 8 + 2 * j;
        *(float2*)(ob0 + col) = make_float2(
            __uint_as_float(f2tf32(o[nt][0] * inv0)),
            __uint_as_float(f2tf32(o[nt][1] * inv0)));
        *(float2*)(ob1 + col) = make_float2(
            __uint_as_float(f2tf32(o[nt][2] * inv1)),
            __uint_as_float(f2tf32(o[nt][3] * inv1)));
    }
}

// ---------------------------------------------------------------------------
extern "C" void kernel_launch(void* const* d_in, const int* in_sizes, int n_in,
                              void* d_out, int out_size)
{
    const float* x      = (const float*)d_in[0];
    const float* w_qkv  = (const float*)d_in[1];
    const float* w_out  = (const float*)d_in[2];
    const int*   ksp    = (const int*)  d_in[3];
    float*       out    = (float*)d_out;

    float *qkv_ptr, *o_ptr, *xt_ptr, *wqt_ptr, *wot_ptr;
    cudaGetSymbolAddress((void**)&qkv_ptr, g_qkv);
    cudaGetSymbolAddress((void**)&o_ptr,   g_o);
    cudaGetSymbolAddress((void**)&xt_ptr,  g_xt);
    cudaGetSymbolAddress((void**)&wqt_ptr, g_wqt);
    cudaGetSymbolAddress((void**)&wot_ptr, g_wot);

    // 0) tf32 pre-conversion of inputs
    cvt_kernel<<<512, 256>>>(x,     xt_ptr,  M_TOT * DMODEL / 4);
    cvt_kernel<<<512, 256>>>(w_qkv, wqt_ptr, QKV_N * DMODEL / 4);
    cvt_kernel<<<256, 256>>>(w_out, wot_ptr, DMODEL * DMODEL / 4);

    // 1) QKV projection (tf32 in, tf32 out)
    {
        dim3 grid(QKV_N / 128, M_TOT / 128);
        gemm_tf32_async<<<grid, 256>>>(xt_ptr, wqt_ptr, qkv_ptr,
                                       M_TOT, QKV_N, DMODEL, 1);
    }

    // 2) Tensor-core neighborhood attention
    {
        dim3 grid(H, NHEADS, NB);
        natten_mma<<<grid, 96>>>(ksp);
    }

    // 3) Output projection (tf32 in, fp32 out)
    {
        dim3 grid(DMODEL / 128, M_TOT / 128);
        gemm_tf32_async<<<grid, 256>>>(o_ptr, wot_ptr, out,
                                       M_TOT, DMODEL, DMODEL, 0);
    }
}